// round 8
// baseline (speedup 1.0000x reference)
#include <cuda_runtime.h>
#include <cuda_bf16.h>

// Problem constants (B=32, S=1024, V=64, H=4096)
#define VOCAB   64
#define HID     4096
#define UOUT    128          // 2*V
#define NBLK    128          // H-split blocks
#define HCHUNK  (HID / NBLK) // 32

// Per-token output index table: out_idx[t] = (scale_idx[t]*t + loc_idx[t]) mod 64
__device__ int    g_table[VOCAB];
// Partial logits scratch: part[t][b][uq], float4 u-quads
__device__ float4 g_part[VOCAB * NBLK * (UOUT / 4)];   // 4 MB

union F2u { unsigned long long u; float2 f; };

// Packed dual-FMA: d = a*b + d on two fp32 lanes.
__device__ __forceinline__ void ffma2(unsigned long long& d,
                                      const unsigned long long a,
                                      const unsigned long long b) {
    asm("fma.rn.f32x2 %0, %1, %2, %3;" : "=l"(d) : "l"(a), "l"(b), "l"(d));
}

// PDL primitives.
__device__ __forceinline__ void pdl_trigger() {
    asm volatile("griddepcontrol.launch_dependents;");
}
__device__ __forceinline__ void pdl_wait() {
    asm volatile("griddepcontrol.wait;" ::: "memory");
}

// ---------------------------------------------------------------------------
// K1: partial logits (R6 config — best measured). Block b owns H-chunk
// [b*32, b*32+32). 512 threads. Triggers dependents at entry so K2 (and
// transitively K3) can start their independent prologues while K1 runs.
// ---------------------------------------------------------------------------
__global__ __launch_bounds__(512, 1)
void partial_kernel(const float* __restrict__ W1, const float* __restrict__ b1,
                    const float* __restrict__ W2) {
    pdl_trigger();

    __shared__ float4 nets2[VOCAB * (HCHUNK / 2)];   // 16 KB [t][hb] dup {n,n,n',n'}
    __shared__ float4 w2s  [HCHUNK * (UOUT / 4)];    // 16 KB [h][uq]

    const int b   = blockIdx.x;
    const int tid = threadIdx.x;
    const int h0  = b * HCHUNK;

    // --- staging: all LDGs issued up front ---
    const int jt = tid >> 3;           // token 0..63
    const int jf = tid & 7;            // float4 within h-chunk
    const float4 w1v = *reinterpret_cast<const float4*>(W1 + jt * HID + h0 + jf * 4);
    const float4 b1v = *reinterpret_cast<const float4*>(b1 + h0 + jf * 4);
    const float4* __restrict__ w2src = reinterpret_cast<const float4*>(W2 + h0 * UOUT);
    const float4 w2a = w2src[tid];
    const float4 w2b = w2src[tid + 512];

    {
        float n0 = fmaxf(w1v.x + b1v.x, 0.f);
        float n1 = fmaxf(w1v.y + b1v.y, 0.f);
        float n2 = fmaxf(w1v.z + b1v.z, 0.f);
        float n3 = fmaxf(w1v.w + b1v.w, 0.f);
        nets2[jt * 16 + jf * 2 + 0] = make_float4(n0, n0, n1, n1);
        nets2[jt * 16 + jf * 2 + 1] = make_float4(n2, n2, n3, n3);
        w2s[tid]       = w2a;
        w2s[tid + 512] = w2b;
    }
    __syncthreads();

    const int uq = tid & 31;           // u-quad 0..31
    const int t0 = (tid >> 5) * 4;     // 4 tokens per thread (16 groups)

    const ulonglong2* __restrict__ n2v = reinterpret_cast<const ulonglong2*>(nets2);
    const ulonglong2* __restrict__ w2v = reinterpret_cast<const ulonglong2*>(w2s);

    unsigned long long acc[4][2];
    #pragma unroll
    for (int t = 0; t < 4; ++t) { acc[t][0] = 0ull; acc[t][1] = 0ull; }

    #pragma unroll
    for (int hb = 0; hb < HCHUNK / 2; ++hb) {              // 2 h per step
        const ulonglong2 w0 = w2v[(2 * hb)     * 32 + uq];
        const ulonglong2 w1 = w2v[(2 * hb + 1) * 32 + uq];
        #pragma unroll
        for (int t = 0; t < 4; ++t) {
            const ulonglong2 nn = n2v[(t0 + t) * 16 + hb]; // broadcast
            ffma2(acc[t][0], nn.x, w0.x);
            ffma2(acc[t][1], nn.x, w0.y);
            ffma2(acc[t][0], nn.y, w1.x);
            ffma2(acc[t][1], nn.y, w1.y);
        }
    }

    #pragma unroll
    for (int t = 0; t < 4; ++t) {
        F2u a0, a1; a0.u = acc[t][0]; a1.u = acc[t][1];
        g_part[((t0 + t) * NBLK + b) * 32 + uq] =
            make_float4(a0.f.x, a0.f.y, a1.f.x, a1.f.y);
    }
}

// ---------------------------------------------------------------------------
// K2: reduce partials over 128 H-blocks, add b2, argmax both halves.
// PDL secondary: trigger K3 immediately, wait for K1's data before reading
// g_part. One block per token, 256 threads.
// ---------------------------------------------------------------------------
__global__ __launch_bounds__(256, 1)
void reduce_kernel(const float* __restrict__ b2) {
    pdl_trigger();                     // let K3 start its input reads now

    __shared__ float red[8][UOUT];
    __shared__ float logits[UOUT];

    const int t    = blockIdx.x;
    const int tid  = threadIdx.x;
    const int warp = tid >> 5;
    const int lane = tid & 31;

    pdl_wait();                        // K1's g_part now visible

    float4 acc = make_float4(0.f, 0.f, 0.f, 0.f);
    const float4* base = &g_part[(t * NBLK) * 32 + lane];
    #pragma unroll 8
    for (int b = warp * 16; b < warp * 16 + 16; ++b) {
        const float4 v = base[b * 32];
        acc.x += v.x; acc.y += v.y; acc.z += v.z; acc.w += v.w;
    }
    red[warp][lane * 4 + 0] = acc.x;
    red[warp][lane * 4 + 1] = acc.y;
    red[warp][lane * 4 + 2] = acc.z;
    red[warp][lane * 4 + 3] = acc.w;
    __syncthreads();

    if (tid < UOUT) {
        float s = b2[tid];
        #pragma unroll
        for (int w = 0; w < 8; ++w) s += red[w][tid];
        logits[tid] = s;
    }
    __syncthreads();

    if (tid == 0) {
        // jnp.argmax keeps the FIRST max -> strict '>' comparison.
        int   li = 0; float lm = logits[0];
        #pragma unroll
        for (int k = 1; k < VOCAB; ++k) if (logits[k] > lm) { lm = logits[k]; li = k; }
        int   si = 0; float sm = logits[VOCAB];
        #pragma unroll
        for (int k = 1; k < VOCAB; ++k) if (logits[VOCAB + k] > sm) { sm = logits[VOCAB + k]; si = k; }
        // loc = first half, scale = second half (jnp.split order)
        g_table[t] = (si * t + li) & (VOCAB - 1);
    }
}

// ---------------------------------------------------------------------------
// K3: full-row writer, MLP=4. PDL secondary: ALL input reads + token
// recovery happen BEFORE the wait (they depend only on the input tensor),
// overlapping K1's tail and all of K2. After the wait: table lookup + 8 MB
// coalesced store.
// ---------------------------------------------------------------------------
#define TOTAL_F4 (32 * 1024 * 64 / 4)   // 524288
#define SC_STRIDE (TOTAL_F4 / 4)        // 131072 (multiple of 16 -> same q per k)

__global__ __launch_bounds__(256)
void out_kernel(const float4* __restrict__ in, float4* __restrict__ out) {
    const int base = blockIdx.x * 256 + threadIdx.x;
    const int q    = base & 15;         // same for all k (stride multiple of 16)

    // ---- pre-wait: input-only work ----
    float4 v[4];
    #pragma unroll
    for (int k = 0; k < 4; ++k) v[k] = in[base + k * SC_STRIDE];

    int tok[4];
    #pragma unroll
    for (int k = 0; k < 4; ++k) {
        int cand = -1;
        if (v[k].x > 0.5f) cand = q * 4 + 0;
        if (v[k].y > 0.5f) cand = q * 4 + 1;
        if (v[k].z > 0.5f) cand = q * 4 + 2;
        if (v[k].w > 0.5f) cand = q * 4 + 3;
        #pragma unroll
        for (int off = 8; off; off >>= 1)
            cand = max(cand, __shfl_xor_sync(0xFFFFFFFFu, cand, off, 16));
        tok[k] = cand;
    }

    // ---- wait for K2's g_table ----
    pdl_wait();

    #pragma unroll
    for (int k = 0; k < 4; ++k) {
        const int oi = g_table[tok[k]]; // uniform broadcast load
        float4 o = make_float4(0.f, 0.f, 0.f, 0.f);
        if ((oi >> 2) == q) reinterpret_cast<float*>(&o)[oi & 3] = 1.0f;
        out[base + k * SC_STRIDE] = o;
    }
}

// ---------------------------------------------------------------------------
extern "C" void kernel_launch(void* const* d_in, const int* in_sizes, int n_in,
                              void* d_out, int out_size) {
    const float* inputs = nullptr;
    const float* W1 = nullptr;
    const float* b1 = nullptr;
    const float* W2 = nullptr;
    const float* b2 = nullptr;

    for (int i = 0; i < n_in; ++i) {
        switch (in_sizes[i]) {
            case 32 * 1024 * 64: inputs = (const float*)d_in[i]; break; // 2097152
            case 64 * 4096:      W1     = (const float*)d_in[i]; break; // 262144
            case 4096:           b1     = (const float*)d_in[i]; break;
            case 4096 * 128:     W2     = (const float*)d_in[i]; break; // 524288
            case 128:            b2     = (const float*)d_in[i]; break;
            default: break;
        }
    }

    // K1: plain launch.
    partial_kernel<<<NBLK, 512>>>(W1, b1, W2);

    // K2: PDL secondary of K1.
    {
        cudaLaunchConfig_t cfg = {};
        cfg.gridDim  = dim3(VOCAB, 1, 1);
        cfg.blockDim = dim3(256, 1, 1);
        cfg.stream   = 0;
        cudaLaunchAttribute a[1];
        a[0].id = cudaLaunchAttributeProgrammaticStreamSerialization;
        a[0].val.programmaticStreamSerializationAllowed = 1;
        cfg.attrs = a; cfg.numAttrs = 1;
        cudaLaunchKernelEx(&cfg, reduce_kernel, b2);
    }

    // K3: PDL secondary of K2.
    {
        cudaLaunchConfig_t cfg = {};
        cfg.gridDim  = dim3(SC_STRIDE / 256, 1, 1);
        cfg.blockDim = dim3(256, 1, 1);
        cfg.stream   = 0;
        cudaLaunchAttribute a[1];
        a[0].id = cudaLaunchAttributeProgrammaticStreamSerialization;
        a[0].val.programmaticStreamSerializationAllowed = 1;
        cfg.attrs = a; cfg.numAttrs = 1;
        cudaLaunchKernelEx(&cfg, out_kernel,
                           reinterpret_cast<const float4*>(inputs),
                           reinterpret_cast<float4*>(d_out));
    }
}